// round 8
// baseline (speedup 1.0000x reference)
#include <cuda_runtime.h>

#define NV 8192          // variable nodes
#define RC 4096          // check nodes
#define DCD 6            // check degree
#define STR 7            // smem slots per check (stride 7 -> conflict-free LDS)
#define EE (NV*3)        // 24576 edges
#define BB 1024          // batch
#define NITER 10
#define TPB 1024
#define NPAIR 432        // CTAs decoding 2 columns (cols 0..863)
#define NSING 160        // CTAs decoding 1 column  (cols 864..1023)

// Small global tables only (messages never touch global memory)
__device__ int            d_cedge[RC*DCD];
__device__ int            d_cnt[RC];          // zero-init; re-zeroed by k_sort each run
__device__ unsigned short d_slotT[NV*4];      // var v -> {slot0, slot1, slot2, pad}

static __device__ __forceinline__ float fex2(float x){ float y; asm("ex2.approx.f32 %0,%1;":"=f"(y):"f"(x)); return y; }
static __device__ __forceinline__ float flg2(float x){ float y; asm("lg2.approx.f32 %0,%1;":"=f"(y):"f"(x)); return y; }

__global__ void k_build(const int* __restrict__ ec){
    int e = blockIdx.x*blockDim.x + threadIdx.x;
    if(e < EE){
        int c = ec[e];
        int s = atomicAdd(&d_cnt[c], 1);
        d_cedge[c*DCD + s] = e;
    }
}

// Sort each check's 6 edge ids (deterministic regardless of atomic order),
// emit packed var->slot table, re-zero d_cnt for the next run.
__global__ void k_sort(){
    int c = blockIdx.x*blockDim.x + threadIdx.x;
    if(c >= RC) return;
    int v[DCD];
#pragma unroll
    for(int j=0;j<DCD;j++) v[j] = d_cedge[c*DCD+j];
#pragma unroll
    for(int i=0;i<DCD-1;i++)
#pragma unroll
        for(int j=0;j<DCD-1-i;j++)
            if(v[j] > v[j+1]){ int t=v[j]; v[j]=v[j+1]; v[j+1]=t; }
#pragma unroll
    for(int j=0;j<DCD;j++){
        int e = v[j];
        int var = e/3, k = e - 3*var;
        d_slotT[var*4 + k] = (unsigned short)(c*STR + j);
    }
    d_cnt[c] = 0;
}

// ---- phase helpers (per column) -------------------------------------------

// init v2c: msg[slot_k(v)] = 2*rec[v]
static __device__ __forceinline__ void ph_init(float* msg, const float* rrow,
                                               const uint2* slt, int tid){
#pragma unroll
    for(int vv = 0; vv < NV/TPB; ++vv){
        int v = vv*TPB + tid;
        uint2 s = slt[v];
        float lv = 2.0f * __ldg(rrow + v);
        msg[s.x & 0xFFFF] = lv;
        msg[s.x >> 16]    = lv;
        msg[s.y & 0xFFFF] = lv;
    }
}

// check phase: msg holds v2c, becomes c2v (in place)
// a_k = sign(x)*(1-e^{-|x|}), b_k = 1+e^{-|x|}  (a/b = tanh(x/2))
// c2v_j = clamp( ln((B_j+A_j)/(B_j-A_j)), +-2*atanh(0.999) )
static __device__ __forceinline__ void ph_check(float* msg, int tid){
#pragma unroll
    for(int cc = 0; cc < RC/TPB; ++cc){
        int base = (cc*TPB + tid)*STR;
        float a[DCD], bb[DCD];
#pragma unroll
        for(int j=0;j<DCD;j++){
            float x = msg[base+j];
            float u = fex2(fabsf(x) * -1.44269504f);
            a[j]  = copysignf(1.0f - u, x);
            bb[j] = 1.0f + u;
        }
        float pa[DCD], pb[DCD];
        pa[0]=1.0f; pb[0]=1.0f;
#pragma unroll
        for(int j=1;j<DCD;j++){ pa[j]=pa[j-1]*a[j-1]; pb[j]=pb[j-1]*bb[j-1]; }
        float sa=1.0f, sb=1.0f;
#pragma unroll
        for(int j=DCD-1;j>=0;j--){
            float A  = pa[j]*sa;
            float Bp = pb[j]*sb;
            sa *= a[j]; sb *= bb[j];
            float mag = 0.69314718f * (flg2(Bp + A) - flg2(Bp - A));
            msg[base+j] = fminf(fmaxf(mag, -7.6004025f), 7.6004025f);  // 2*atanh(0.999)
        }
    }
}

// var phase: msg holds c2v, becomes v2c (in place)
static __device__ __forceinline__ void ph_var(float* msg, const float* rrow,
                                              const uint2* slt, int tid){
#pragma unroll
    for(int vv = 0; vv < NV/TPB; ++vv){
        int v = vv*TPB + tid;
        uint2 s = slt[v];
        int s0 = s.x & 0xFFFF, s1 = s.x >> 16, s2 = s.y & 0xFFFF;
        float c0 = msg[s0], c1 = msg[s1], c2 = msg[s2];
        float t = 2.0f * __ldg(rrow + v) + c0 + c1 + c2;
        msg[s0] = t - c0;
        msg[s1] = t - c1;
        msg[s2] = t - c2;
    }
}

// final posterior + bits
static __device__ __forceinline__ void ph_final(const float* msg, const float* rrow,
                                                float* orow, float* brow,
                                                const uint2* slt, int tid, int do_bits){
#pragma unroll
    for(int vv = 0; vv < NV/TPB; ++vv){
        int v = vv*TPB + tid;
        uint2 s = slt[v];
        float f = 2.0f * __ldg(rrow + v)
                + msg[s.x & 0xFFFF] + msg[s.x >> 16] + msg[s.y & 0xFFFF];
        orow[v] = f;
        if(do_bits) brow[v] = (f < 0.0f) ? 1.0f : 0.0f;
    }
}

// ---- pair kernel: 2 columns per CTA, phases software-pipelined ------------
// Every sync-delimited stage runs one check phase (MUFU-heavy) and one var
// phase (crossbar-heavy) so both pipes stay busy.
__global__ void __launch_bounds__(TPB, 1) k_decode2(const float* __restrict__ rec,
                                                    float* __restrict__ out,
                                                    int do_bits){
    extern __shared__ float sm[];
    float* msgA = sm;
    float* msgB = sm + RC*STR;

    const int tid = threadIdx.x;
    const int ca = 2*blockIdx.x, cb = ca + 1;
    const float* rA = rec + (size_t)ca*NV;
    const float* rB = rec + (size_t)cb*NV;
    const uint2* slt = (const uint2*)d_slotT;

    ph_init(msgA, rA, slt, tid);
    __syncthreads();
    ph_check(msgA, tid);  ph_init(msgB, rB, slt, tid);   // A.c1 | B.init
    __syncthreads();
#pragma unroll 1
    for(int it = 1; it <= NITER-1; ++it){
        ph_check(msgB, tid);  ph_var(msgA, rA, slt, tid);  // B.c_it | A.v_it
        __syncthreads();
        ph_check(msgA, tid);  ph_var(msgB, rB, slt, tid);  // A.c_{it+1} | B.v_it
        __syncthreads();
    }
    // A has completed c10; B has completed v9.
    ph_check(msgB, tid);                                   // B.c10
    ph_final(msgA, rA, out + (size_t)ca*NV, out + (size_t)(BB + ca)*NV, slt, tid, do_bits);
    __syncthreads();
    ph_final(msgB, rB, out + (size_t)cb*NV, out + (size_t)(BB + cb)*NV, slt, tid, do_bits);
}

// ---- single kernel: 1 column per CTA (remainder columns) ------------------
__global__ void __launch_bounds__(TPB, 1) k_decode1(const float* __restrict__ rec,
                                                    float* __restrict__ out,
                                                    int do_bits){
    extern __shared__ float sm[];
    float* msg = sm;

    const int tid = threadIdx.x;
    const int b = 2*NPAIR + blockIdx.x;
    const float* rrow = rec + (size_t)b*NV;
    const uint2* slt = (const uint2*)d_slotT;

    ph_init(msg, rrow, slt, tid);
    __syncthreads();
#pragma unroll 1
    for(int it = 1; it <= NITER; ++it){
        ph_check(msg, tid);
        __syncthreads();
        if(it == NITER) break;
        ph_var(msg, rrow, slt, tid);
        __syncthreads();
    }
    ph_final(msg, rrow, out + (size_t)b*NV, out + (size_t)(BB + b)*NV, slt, tid, do_bits);
}

extern "C" void kernel_launch(void* const* d_in, const int* in_sizes, int n_in,
                              void* d_out, int out_size){
    const float* rec = (const float*)d_in[0];
    const int*   ec  = (const int*)d_in[2];   // edge_check (edge_var is repeat(arange(N),3))

    static const int SMEM2 = 2*RC*STR*4;       // 229376 B
    static const int SMEM1 = RC*STR*4;         // 114688 B
    cudaFuncSetAttribute(k_decode2, cudaFuncAttributeMaxDynamicSharedMemorySize, SMEM2);
    cudaFuncSetAttribute(k_decode1, cudaFuncAttributeMaxDynamicSharedMemorySize, SMEM1);

    k_build<<<EE/256, 256>>>(ec);
    k_sort<<<RC/256, 256>>>();

    int do_bits = (out_size >= 2*NV*BB);
    k_decode2<<<NPAIR, TPB, SMEM2>>>(rec, (float*)d_out, do_bits);
    k_decode1<<<NSING, TPB, SMEM1>>>(rec, (float*)d_out, do_bits);
}

// round 9
// speedup vs baseline: 1.0662x; 1.0662x over previous
#include <cuda_runtime.h>

#define NV 8192          // variable nodes
#define RC 4096          // check nodes
#define DCD 6            // check degree
#define STR 7            // slots per check (stride 7 -> conflict-free scalar LDS)
#define EE (NV*3)        // 24576 edges
#define BB 1024          // batch
#define NITER 10
#define TPB 1024
#define NCTA (BB/2)      // 512 CTAs, 2 columns each

// Small global tables only (messages never touch global memory)
__device__ int            d_cedge[RC*DCD];
__device__ int            d_cnt[RC];          // zero-init; re-zeroed by k_sort each run
__device__ unsigned short d_slotT[NV*4];      // var v -> {slot0, slot1, slot2, pad}

static __device__ __forceinline__ float fex2(float x){ float y; asm("ex2.approx.f32 %0,%1;":"=f"(y):"f"(x)); return y; }
static __device__ __forceinline__ float flg2(float x){ float y; asm("lg2.approx.f32 %0,%1;":"=f"(y):"f"(x)); return y; }

__global__ void k_build(const int* __restrict__ ec){
    int e = blockIdx.x*blockDim.x + threadIdx.x;
    if(e < EE){
        int c = ec[e];
        int s = atomicAdd(&d_cnt[c], 1);
        d_cedge[c*DCD + s] = e;
    }
}

// Sort each check's 6 edge ids (deterministic regardless of atomic order),
// emit packed var->slot table, re-zero d_cnt for the next run.
__global__ void k_sort(){
    int c = blockIdx.x*blockDim.x + threadIdx.x;
    if(c >= RC) return;
    int v[DCD];
#pragma unroll
    for(int j=0;j<DCD;j++) v[j] = d_cedge[c*DCD+j];
#pragma unroll
    for(int i=0;i<DCD-1;i++)
#pragma unroll
        for(int j=0;j<DCD-1-i;j++)
            if(v[j] > v[j+1]){ int t=v[j]; v[j]=v[j+1]; v[j+1]=t; }
#pragma unroll
    for(int j=0;j<DCD;j++){
        int e = v[j];
        int var = e/3, k = e - 3*var;
        d_slotT[var*4 + k] = (unsigned short)(c*STR + j);
    }
    d_cnt[c] = 0;
}

// Scalar check-node math: in x[6] (v2c), out o[6] (c2v).
// a_k = sign(x)*(1-e^{-|x|}), b_k = 1+e^{-|x|}  (a/b = tanh(x/2));
// leave-one-out via prefix/suffix products (division-free);
// c2v_j = clamp( ln((B_j+A_j)/(B_j-A_j)), +-2*atanh(0.999) )
static __device__ __forceinline__ void chk_math(const float* x, float* o){
    float a[DCD], bb[DCD];
#pragma unroll
    for(int j=0;j<DCD;j++){
        float u = fex2(fabsf(x[j]) * -1.44269504f);
        a[j]  = copysignf(1.0f - u, x[j]);
        bb[j] = 1.0f + u;
    }
    float pa[DCD], pb[DCD];
    pa[0]=1.0f; pb[0]=1.0f;
#pragma unroll
    for(int j=1;j<DCD;j++){ pa[j]=pa[j-1]*a[j-1]; pb[j]=pb[j-1]*bb[j-1]; }
    float sa=1.0f, sb=1.0f;
#pragma unroll
    for(int j=DCD-1;j>=0;j--){
        float A  = pa[j]*sa;
        float Bp = pb[j]*sb;
        sa *= a[j]; sb *= bb[j];
        float mag = 0.69314718f * (flg2(Bp + A) - flg2(Bp - A));
        o[j] = fminf(fmaxf(mag, -7.6004025f), 7.6004025f);   // 2*atanh(0.999)
    }
}

// Two batch columns fused into one float2 message array: every LDS/STS is
// 64-bit and serves both columns; all indexing amortized 2x.
__global__ void __launch_bounds__(TPB, 1) k_decode(const float* __restrict__ rec,
                                                   float* __restrict__ out,
                                                   int do_bits){
    extern __shared__ float2 msg2[];               // RC*STR float2 = 224KB

    const int tid = threadIdx.x;
    const int ca = 2*blockIdx.x, cb = ca + 1;
    const float* __restrict__ rA = rec + (size_t)ca*NV;
    const float* __restrict__ rB = rec + (size_t)cb*NV;
    const uint2* __restrict__ slt = (const uint2*)d_slotT;   // {s0|s1, s2|pad}

    // Init v2c: msg2[slot_k(v)] = {2*recA[v], 2*recB[v]}
#pragma unroll
    for(int vv = 0; vv < NV/TPB; ++vv){
        int v = vv*TPB + tid;
        uint2 s = slt[v];
        float2 lv = make_float2(2.0f*__ldg(rA+v), 2.0f*__ldg(rB+v));
        msg2[s.x & 0xFFFF] = lv;
        msg2[s.x >> 16]    = lv;
        msg2[s.y & 0xFFFF] = lv;
    }
    __syncthreads();

#pragma unroll 1
    for(int it = 1; it <= NITER; ++it){
        // ---- check phase (both columns) ----
#pragma unroll
        for(int cc = 0; cc < RC/TPB; ++cc){
            int base = (cc*TPB + tid)*STR;
            float2 X2[DCD];
#pragma unroll
            for(int j=0;j<DCD;j++) X2[j] = msg2[base+j];
            float x[DCD], ox[DCD], oy[DCD];
#pragma unroll
            for(int j=0;j<DCD;j++) x[j] = X2[j].x;
            chk_math(x, ox);
#pragma unroll
            for(int j=0;j<DCD;j++) x[j] = X2[j].y;
            chk_math(x, oy);
#pragma unroll
            for(int j=0;j<DCD;j++) msg2[base+j] = make_float2(ox[j], oy[j]);
        }
        __syncthreads();

        if(it == NITER) break;

        // ---- var phase (both columns) ----
#pragma unroll
        for(int vv = 0; vv < NV/TPB; ++vv){
            int v = vv*TPB + tid;
            uint2 s = slt[v];
            int s0 = s.x & 0xFFFF, s1 = s.x >> 16, s2 = s.y & 0xFFFF;
            float2 c0 = msg2[s0], c1 = msg2[s1], c2 = msg2[s2];
            float tx = 2.0f*__ldg(rA+v) + c0.x + c1.x + c2.x;
            float ty = 2.0f*__ldg(rB+v) + c0.y + c1.y + c2.y;
            msg2[s0] = make_float2(tx - c0.x, ty - c0.y);
            msg2[s1] = make_float2(tx - c1.x, ty - c1.y);
            msg2[s2] = make_float2(tx - c2.x, ty - c2.y);
        }
        __syncthreads();
    }

    // Final posterior + bits for both columns (coalesced rows)
    float* oA = out + (size_t)ca*NV;  float* bA = out + (size_t)(BB+ca)*NV;
    float* oB = out + (size_t)cb*NV;  float* bB = out + (size_t)(BB+cb)*NV;
#pragma unroll
    for(int vv = 0; vv < NV/TPB; ++vv){
        int v = vv*TPB + tid;
        uint2 s = slt[v];
        float2 c0 = msg2[s.x & 0xFFFF], c1 = msg2[s.x >> 16], c2 = msg2[s.y & 0xFFFF];
        float fx = 2.0f*__ldg(rA+v) + c0.x + c1.x + c2.x;
        float fy = 2.0f*__ldg(rB+v) + c0.y + c1.y + c2.y;
        oA[v] = fx;  oB[v] = fy;
        if(do_bits){ bA[v] = (fx < 0.0f) ? 1.0f : 0.0f;
                     bB[v] = (fy < 0.0f) ? 1.0f : 0.0f; }
    }
}

extern "C" void kernel_launch(void* const* d_in, const int* in_sizes, int n_in,
                              void* d_out, int out_size){
    const float* rec = (const float*)d_in[0];
    const int*   ec  = (const int*)d_in[2];   // edge_check (edge_var is repeat(arange(N),3))

    static const int SMEM = RC*STR*8;          // 229376 B (float2 messages)
    cudaFuncSetAttribute(k_decode, cudaFuncAttributeMaxDynamicSharedMemorySize, SMEM);

    k_build<<<EE/256, 256>>>(ec);
    k_sort<<<RC/256, 256>>>();

    int do_bits = (out_size >= 2*NV*BB);
    k_decode<<<NCTA, TPB, SMEM>>>(rec, (float*)d_out, do_bits);
}

// round 12
// speedup vs baseline: 1.2943x; 1.2140x over previous
#include <cuda_runtime.h>

#define NV 8192          // variable nodes
#define RC 4096          // check nodes
#define DCD 6            // check degree
#define STR 7            // slots per check (stride 7 -> conflict-free contiguous LDS)
#define EE (NV*3)        // 24576 edges
#define BB 1024          // batch
#define NITER 10
#define TPB 1024         // 32 warps: 16 check-role + 16 var-role
#define HALF 512         // threads per role
#define NCTA (BB/2)      // 512 CTAs, 2 columns each

// Small global tables only (messages never touch global memory)
__device__ int            d_cedge[RC*DCD];
__device__ int            d_cnt[RC];          // zero-init; re-zeroed by k_sort each run
__device__ unsigned short d_slotT[NV*4];      // var v -> {slot0, slot1, slot2, pad}

static __device__ __forceinline__ float fex2(float x){ float y; asm("ex2.approx.f32 %0,%1;":"=f"(y):"f"(x)); return y; }
static __device__ __forceinline__ float flg2(float x){ float y; asm("lg2.approx.f32 %0,%1;":"=f"(y):"f"(x)); return y; }

__global__ void k_build(const int* __restrict__ ec){
    int e = blockIdx.x*blockDim.x + threadIdx.x;
    if(e < EE){
        int c = ec[e];
        int s = atomicAdd(&d_cnt[c], 1);
        d_cedge[c*DCD + s] = e;
    }
}

// Sort each check's 6 edge ids (deterministic regardless of atomic order),
// emit packed var->slot table, re-zero d_cnt for the next run.
__global__ void k_sort(){
    int c = blockIdx.x*blockDim.x + threadIdx.x;
    if(c >= RC) return;
    int v[DCD];
#pragma unroll
    for(int j=0;j<DCD;j++) v[j] = d_cedge[c*DCD+j];
#pragma unroll
    for(int i=0;i<DCD-1;i++)
#pragma unroll
        for(int j=0;j<DCD-1-i;j++)
            if(v[j] > v[j+1]){ int t=v[j]; v[j]=v[j+1]; v[j+1]=t; }
#pragma unroll
    for(int j=0;j<DCD;j++){
        int e = v[j];
        int var = e/3, k = e - 3*var;
        d_slotT[var*4 + k] = (unsigned short)(c*STR + j);
    }
    d_cnt[c] = 0;
}

// ---- role helpers (NT = threads cooperating, t in [0,NT)) -----------------

// Check-node update for ALL RC checks.
// a_k = sign(x)*(1-e^{-|x|}), b_k = 1+e^{-|x|}  (a/b = tanh(x/2));
// c2v_j = clamp( ln((B_j+A_j)/(B_j-A_j)), +-2*atanh(0.999) )  via prefix/suffix.
template<int NT>
static __device__ __forceinline__ void check_sub(float* msg, int t){
#pragma unroll
    for(int cc = 0; cc < RC/NT; ++cc){
        int base = (cc*NT + t)*STR;
        float a[DCD], bb[DCD];
#pragma unroll
        for(int j=0;j<DCD;j++){
            float x = msg[base+j];
            float u = fex2(fabsf(x) * -1.44269504f);
            a[j]  = copysignf(1.0f - u, x);
            bb[j] = 1.0f + u;
        }
        float pa[DCD], pb[DCD];
        pa[0]=1.0f; pb[0]=1.0f;
#pragma unroll
        for(int j=1;j<DCD;j++){ pa[j]=pa[j-1]*a[j-1]; pb[j]=pb[j-1]*bb[j-1]; }
        float sa=1.0f, sb=1.0f;
#pragma unroll
        for(int j=DCD-1;j>=0;j--){
            float A  = pa[j]*sa;
            float Bp = pb[j]*sb;
            sa *= a[j]; sb *= bb[j];
            float mag = 0.69314718f * (flg2(Bp + A) - flg2(Bp - A));
            msg[base+j] = fminf(fmaxf(mag, -7.6004025f), 7.6004025f);  // 2*atanh(0.999)
        }
    }
}

// Var-node update for ALL NV vars.
template<int NT>
static __device__ __forceinline__ void var_sub(float* msg, const float* __restrict__ rrow,
                                               const uint2* __restrict__ slt, int t){
#pragma unroll
    for(int vv = 0; vv < NV/NT; ++vv){
        int v = vv*NT + t;
        uint2 s = slt[v];
        int s0 = s.x & 0xFFFF, s1 = s.x >> 16, s2 = s.y & 0xFFFF;
        float c0 = msg[s0], c1 = msg[s1], c2 = msg[s2];
        float tot = 2.0f*__ldg(rrow+v) + c0 + c1 + c2;
        msg[s0] = tot - c0;
        msg[s1] = tot - c1;
        msg[s2] = tot - c2;
    }
}

// Init v2c for ALL NV vars.
template<int NT>
static __device__ __forceinline__ void init_sub(float* msg, const float* __restrict__ rrow,
                                                const uint2* __restrict__ slt, int t){
#pragma unroll
    for(int vv = 0; vv < NV/NT; ++vv){
        int v = vv*NT + t;
        uint2 s = slt[v];
        float lv = 2.0f * __ldg(rrow+v);
        msg[s.x & 0xFFFF] = lv;
        msg[s.x >> 16]    = lv;
        msg[s.y & 0xFFFF] = lv;
    }
}

// Final posterior + bits for ALL NV vars.
template<int NT>
static __device__ __forceinline__ void final_sub(const float* msg, const float* __restrict__ rrow,
                                                 float* __restrict__ orow, float* __restrict__ brow,
                                                 const uint2* __restrict__ slt, int t, int do_bits){
#pragma unroll
    for(int vv = 0; vv < NV/NT; ++vv){
        int v = vv*NT + t;
        uint2 s = slt[v];
        float f = 2.0f*__ldg(rrow+v)
                + msg[s.x & 0xFFFF] + msg[s.x >> 16] + msg[s.y & 0xFFFF];
        orow[v] = f;
        if(do_bits) brow[v] = (f < 0.0f) ? 1.0f : 0.0f;
    }
}

// ---- warp-specialized pair kernel -----------------------------------------
// 2 columns per CTA (msgA, msgB, 224KB). Warps 0-15 = check role, 16-31 = var
// role. Every stage runs a check phase (MUFU pipe) and a var phase (smem
// crossbar) CONCURRENTLY on different warps -> pipes overlap instead of adding.
__global__ void __launch_bounds__(TPB, 1) k_decode(const float* __restrict__ rec,
                                                   float* __restrict__ out,
                                                   int do_bits){
    extern __shared__ float sm[];
    float* msgA = sm;
    float* msgB = sm + RC*STR;

    const int tid = threadIdx.x;
    const int ca = 2*blockIdx.x, cb = ca + 1;
    const float* __restrict__ rA = rec + (size_t)ca*NV;
    const float* __restrict__ rB = rec + (size_t)cb*NV;
    const uint2* __restrict__ slt = (const uint2*)d_slotT;   // {s0|s1, s2|pad}

    const bool chkrole = (tid < HALF);                       // warps 0-15
    const int t = chkrole ? tid : (tid - HALF);              // 0..511 within role

    // stage 1: init A (all 1024 threads)
    init_sub<TPB>(msgA, rA, slt, tid);
    __syncthreads();

    // stage 2: check A(it1) || init B
    if(chkrole) check_sub<HALF>(msgA, t); else init_sub<HALF>(msgB, rB, slt, t);
    __syncthreads();

    // stages 3..20: { check B(it) || var A(it) ; check A(it+1) || var B(it) }
#pragma unroll 1
    for(int it = 1; it <= NITER-1; ++it){
        if(chkrole) check_sub<HALF>(msgB, t); else var_sub<HALF>(msgA, rA, slt, t);
        __syncthreads();
        if(chkrole) check_sub<HALF>(msgA, t); else var_sub<HALF>(msgB, rB, slt, t);
        __syncthreads();
    }
    // A: check10 done.  B: var9 done.
    // stage 21: check B(it10) || final A
    if(chkrole) check_sub<HALF>(msgB, t);
    else final_sub<HALF>(msgA, rA, out + (size_t)ca*NV, out + (size_t)(BB+ca)*NV, slt, t, do_bits);
    __syncthreads();
    // stage 22: final B (all 1024 threads)
    final_sub<TPB>(msgB, rB, out + (size_t)cb*NV, out + (size_t)(BB+cb)*NV, slt, tid, do_bits);
}

extern "C" void kernel_launch(void* const* d_in, const int* in_sizes, int n_in,
                              void* d_out, int out_size){
    const float* rec = (const float*)d_in[0];
    const int*   ec  = (const int*)d_in[2];   // edge_check (edge_var is repeat(arange(N),3))

    static const int SMEM = 2*RC*STR*4;        // 229376 B (two message arrays)
    cudaFuncSetAttribute(k_decode, cudaFuncAttributeMaxDynamicSharedMemorySize, SMEM);

    k_build<<<EE/256, 256>>>(ec);
    k_sort<<<RC/256, 256>>>();

    int do_bits = (out_size >= 2*NV*BB);
    k_decode<<<NCTA, TPB, SMEM>>>(rec, (float*)d_out, do_bits);
}